// round 6
// baseline (speedup 1.0000x reference)
#include <cuda_runtime.h>
#include <cstddef>

#define BATCH 8
#define HWP   65536
#define PB    4194304            // 64*65536 floats per batch
#define KDIM  16384
#define NROW  256
#define SPLIT 32
#define KCH   (KDIM / SPLIT)     // 512

__device__ float g_part[(size_t)SPLIT * BATCH * NROW * NROW];
__device__ float g_sr[BATCH * NROW];
__device__ float g_sx[BATCH * NROW];
__device__ float g_f [BATCH * NROW * NROW];
__device__ float g_U [BATCH * NROW * NROW];
__device__ float g_bp[BATCH * 4 * NROW];
__device__ float g_y4[(size_t)BATCH * PB];

// ------------------------------------------------------------- K0: row sums
__global__ void k0_rowsum(const float* __restrict__ x, const float* __restrict__ ref) {
    int r = blockIdx.x, b = blockIdx.y, which = blockIdx.z;
    const float* src = which ? x : ref;
    const float4* p = reinterpret_cast<const float4*>(src + (size_t)b * PB + (size_t)r * KDIM);
    float s = 0.f;
    for (int i = threadIdx.x; i < KDIM / 4; i += 256) {
        float4 v = p[i];
        s += (v.x + v.y) + (v.z + v.w);
    }
    __shared__ float red[256];
    red[threadIdx.x] = s;
    __syncthreads();
    for (int o = 128; o > 0; o >>= 1) {
        if (threadIdx.x < o) red[threadIdx.x] += red[threadIdx.x + o];
        __syncthreads();
    }
    if (threadIdx.x == 0) (which ? g_sx : g_sr)[b * NROW + r] = red[0];
}

// -------------------------------------------- K1: G = ref2 @ x2^T  (split-K)
__global__ void __launch_bounds__(256) k1_gram(const float* __restrict__ ref,
                                               const float* __restrict__ x) {
    const int ti = blockIdx.x >> 1, tj = blockIdx.x & 1;
    const int b = blockIdx.y, sp = blockIdx.z;
    const float* A  = ref + (size_t)b * PB + (size_t)(ti * 128) * KDIM + sp * KCH;
    const float* Bp = x   + (size_t)b * PB + (size_t)(tj * 128) * KDIM + sp * KCH;

    __shared__ float As[2][8][132];
    __shared__ float Bs[2][8][132];

    const int t  = threadIdx.x;
    const int lr = t >> 1;
    const int lq = (t & 1) * 4;
    const int ty = t >> 4, tx = t & 15;

    float acc[8][8];
#pragma unroll
    for (int u = 0; u < 8; u++)
#pragma unroll
        for (int v = 0; v < 8; v++) acc[u][v] = 0.f;

    float4 av = *reinterpret_cast<const float4*>(A  + (size_t)lr * KDIM + lq);
    float4 bv = *reinterpret_cast<const float4*>(Bp + (size_t)lr * KDIM + lq);
    As[0][lq+0][lr]=av.x; As[0][lq+1][lr]=av.y; As[0][lq+2][lr]=av.z; As[0][lq+3][lr]=av.w;
    Bs[0][lq+0][lr]=bv.x; Bs[0][lq+1][lr]=bv.y; Bs[0][lq+2][lr]=bv.z; Bs[0][lq+3][lr]=bv.w;
    __syncthreads();

    const int NIT = KCH / 8;
    for (int kk = 0; kk < NIT; ++kk) {
        const int cur = kk & 1, nxt = cur ^ 1;
        if (kk + 1 < NIT) {
            av = *reinterpret_cast<const float4*>(A  + (size_t)lr * KDIM + (kk+1)*8 + lq);
            bv = *reinterpret_cast<const float4*>(Bp + (size_t)lr * KDIM + (kk+1)*8 + lq);
        }
#pragma unroll
        for (int k = 0; k < 8; k++) {
            float af[8], bf[8];
            *reinterpret_cast<float4*>(af)     = *reinterpret_cast<const float4*>(&As[cur][k][ty*4]);
            *reinterpret_cast<float4*>(af + 4) = *reinterpret_cast<const float4*>(&As[cur][k][64 + ty*4]);
            *reinterpret_cast<float4*>(bf)     = *reinterpret_cast<const float4*>(&Bs[cur][k][tx*4]);
            *reinterpret_cast<float4*>(bf + 4) = *reinterpret_cast<const float4*>(&Bs[cur][k][64 + tx*4]);
#pragma unroll
            for (int u = 0; u < 8; u++)
#pragma unroll
                for (int v = 0; v < 8; v++) acc[u][v] = fmaf(af[u], bf[v], acc[u][v]);
        }
        if (kk + 1 < NIT) {
            As[nxt][lq+0][lr]=av.x; As[nxt][lq+1][lr]=av.y; As[nxt][lq+2][lr]=av.z; As[nxt][lq+3][lr]=av.w;
            Bs[nxt][lq+0][lr]=bv.x; Bs[nxt][lq+1][lr]=bv.y; Bs[nxt][lq+2][lr]=bv.z; Bs[nxt][lq+3][lr]=bv.w;
        }
        __syncthreads();
    }

    float* outp = g_part + ((size_t)sp * BATCH + b) * ((size_t)NROW * NROW);
#pragma unroll
    for (int u = 0; u < 8; u++) {
        int row = ti * 128 + (u < 4 ? ty*4 + u : 64 + ty*4 + (u - 4));
        float4 w0 = make_float4(acc[u][0], acc[u][1], acc[u][2], acc[u][3]);
        float4 w1 = make_float4(acc[u][4], acc[u][5], acc[u][6], acc[u][7]);
        *reinterpret_cast<float4*>(outp + (size_t)row * NROW + tj*128 + tx*4)      = w0;
        *reinterpret_cast<float4*>(outp + (size_t)row * NROW + tj*128 + 64 + tx*4) = w1;
    }
}

// ---------------- K2a: f = Wth' G Wph'^T + conv-bias rank-1 terms
__global__ void k2a_f(const float* __restrict__ wth, const float* __restrict__ bth,
                      const float* __restrict__ wph, const float* __restrict__ bph) {
    const int hb1 = blockIdx.x >> 2, hb2 = blockIdx.x & 3, b = blockIdx.y;
    __shared__ float S[64][64];
    __shared__ float T[64][64];
    __shared__ float ths[64], phs[64];
    const int t = threadIdx.x;

    for (int idx = t; idx < 4096; idx += 256) {
        int c = idx >> 6, cp = idx & 63;
        size_t off = (size_t)b * 65536 + (size_t)(c*4 + hb1) * 256 + cp*4 + hb2;
        float a = 0.f;
#pragma unroll 8
        for (int s = 0; s < SPLIT; s++) a += g_part[(size_t)s * (BATCH * 65536) + off];
        S[c][cp] = a;
    }
    __syncthreads();

    for (int idx = t; idx < 4096; idx += 256) {
        int ci = idx >> 6, cp = idx & 63;
        float a = 0.f;
#pragma unroll
        for (int c = 0; c < 64; c++) a = fmaf(__ldg(&wth[ci*64 + c]), S[c][cp], a);
        T[ci][cp] = a;
    }
    __syncthreads();

    if (t < 64) {
        float a = 0.f;
        for (int c = 0; c < 64; c++) a = fmaf(wth[t*64 + c], g_sr[b*256 + c*4 + hb1], a);
        ths[t] = a;
    } else if (t < 128) {
        int ci = t - 64;
        float a = 0.f;
        for (int cp = 0; cp < 64; cp++) a = fmaf(wph[ci*64 + cp], g_sx[b*256 + cp*4 + hb2], a);
        phs[ci] = a;
    }
    for (int idx = t; idx < 4096; idx += 256) {
        int ci2 = idx >> 6, cp = idx & 63;
        S[cp][ci2] = wph[idx];
    }
    __syncthreads();

    for (int idx = t; idx < 4096; idx += 256) {
        int ci1 = idx >> 6, ci2 = idx & 63;
        float a = 0.f;
#pragma unroll
        for (int cp = 0; cp < 64; cp++) a = fmaf(T[ci1][cp], S[cp][ci2], a);
        float bt = __ldg(&bth[ci1]), bp = __ldg(&bph[ci2]);
        a += bt * phs[ci2] + ths[ci1] * bp + 16384.f * bt * bp;
        g_f[(size_t)b * 65536 + (size_t)(ci1*4 + hb1) * 256 + ci2*4 + hb2] = a;
    }
}

// ---------------- K2b: softmax over rows (axis=1), per column
__global__ void k2b_softmax() {
    const int b = blockIdx.y;
    const int col = blockIdx.x * 8 + (threadIdx.x >> 5);
    const int lane = threadIdx.x & 31;
    float* F = g_f + (size_t)b * 65536;
    float v[8];
#pragma unroll
    for (int s = 0; s < 8; s++) v[s] = F[(s*32 + lane) * 256 + col];
    float m = v[0];
#pragma unroll
    for (int s = 1; s < 8; s++) m = fmaxf(m, v[s]);
#pragma unroll
    for (int o = 16; o > 0; o >>= 1) m = fmaxf(m, __shfl_xor_sync(0xffffffffu, m, o));
    float sum = 0.f;
#pragma unroll
    for (int s = 0; s < 8; s++) { v[s] = expf(v[s] - m); sum += v[s]; }
#pragma unroll
    for (int o = 16; o > 0; o >>= 1) sum += __shfl_xor_sync(0xffffffffu, sum, o);
    float r = 1.f / sum;
#pragma unroll
    for (int s = 0; s < 8; s++) F[(s*32 + lane) * 256 + col] = v[s] * r;
}

// ---------------- K2c: U = fdiv * Wg-blockdiag, beta partials
__global__ void k2c_u(const float* __restrict__ wg, const float* __restrict__ bg) {
    const int hb2 = blockIdx.x, b = blockIdx.y;
    __shared__ float wgs[64][64];
    for (int idx = threadIdx.x; idx < 4096; idx += 256) wgs[idx >> 6][idx & 63] = wg[idx];
    __syncthreads();
    const int i = threadIdx.x;
    const float* F = g_f + (size_t)b * 65536 + (size_t)i * 256 + hb2;
    float frow[64];
#pragma unroll
    for (int ci = 0; ci < 64; ci++) frow[ci] = F[ci * 4];
    float* U = g_U + (size_t)b * 65536 + (size_t)i * 256 + hb2;
    for (int c = 0; c < 64; c++) {
        float a = 0.f;
#pragma unroll
        for (int ci = 0; ci < 64; ci++) a = fmaf(frow[ci], wgs[ci][c], a);
        U[c * 4] = a;
    }
    float bs = 0.f;
#pragma unroll
    for (int ci = 0; ci < 64; ci++) bs = fmaf(frow[ci], __ldg(&bg[ci]), bs);
    g_bp[((size_t)b * 4 + hb2) * 256 + i] = bs;
}

// ---------------- K3: Y4 = x2^T @ U^T + beta  (lands in NCHW layout)
__global__ void __launch_bounds__(256) k3_y(const float* __restrict__ x) {
    const int nt = blockIdx.x & 1, mt = blockIdx.x >> 1;
    const int b = blockIdx.y;
    const int m0 = mt * 128, n0 = nt * 128;
    const float* xp = x   + (size_t)b * PB;
    const float* Up = g_U + (size_t)b * 65536;

    __shared__ float As[2][8][132];
    __shared__ float Bs[2][8][132];

    const int t = threadIdx.x;
    const int akq = t >> 5, am4 = (t & 31) * 4;
    const int bn = t >> 1, bkq = (t & 1) * 4;
    const int ty = t >> 4, tx = t & 15;

    float acc[8][8];
#pragma unroll
    for (int u = 0; u < 8; u++)
#pragma unroll
        for (int v = 0; v < 8; v++) acc[u][v] = 0.f;

    float4 av = *reinterpret_cast<const float4*>(xp + (size_t)akq * KDIM + m0 + am4);
    float4 bv = *reinterpret_cast<const float4*>(Up + (size_t)(n0 + bn) * 256 + bkq);
    *reinterpret_cast<float4*>(&As[0][akq][am4]) = av;
    Bs[0][bkq+0][bn]=bv.x; Bs[0][bkq+1][bn]=bv.y; Bs[0][bkq+2][bn]=bv.z; Bs[0][bkq+3][bn]=bv.w;
    __syncthreads();

    const int NIT = 256 / 8;
    for (int kk = 0; kk < NIT; ++kk) {
        const int cur = kk & 1, nxt = cur ^ 1;
        if (kk + 1 < NIT) {
            av = *reinterpret_cast<const float4*>(xp + (size_t)((kk+1)*8 + akq) * KDIM + m0 + am4);
            bv = *reinterpret_cast<const float4*>(Up + (size_t)(n0 + bn) * 256 + (kk+1)*8 + bkq);
        }
#pragma unroll
        for (int k = 0; k < 8; k++) {
            float af[8], bf[8];
            *reinterpret_cast<float4*>(af)     = *reinterpret_cast<const float4*>(&As[cur][k][ty*4]);
            *reinterpret_cast<float4*>(af + 4) = *reinterpret_cast<const float4*>(&As[cur][k][64 + ty*4]);
            *reinterpret_cast<float4*>(bf)     = *reinterpret_cast<const float4*>(&Bs[cur][k][tx*4]);
            *reinterpret_cast<float4*>(bf + 4) = *reinterpret_cast<const float4*>(&Bs[cur][k][64 + tx*4]);
#pragma unroll
            for (int u = 0; u < 8; u++)
#pragma unroll
                for (int v = 0; v < 8; v++) acc[u][v] = fmaf(af[u], bf[v], acc[u][v]);
        }
        if (kk + 1 < NIT) {
            *reinterpret_cast<float4*>(&As[nxt][akq][am4]) = av;
            Bs[nxt][bkq+0][bn]=bv.x; Bs[nxt][bkq+1][bn]=bv.y; Bs[nxt][bkq+2][bn]=bv.z; Bs[nxt][bkq+3][bn]=bv.w;
        }
        __syncthreads();
    }

    float bn8[8];
#pragma unroll
    for (int v = 0; v < 8; v++) {
        int n = n0 + (v < 4 ? tx*4 + v : 64 + tx*4 + (v - 4));
        bn8[v] = g_bp[((size_t)b*4 + 0)*256 + n] + g_bp[((size_t)b*4 + 1)*256 + n]
               + g_bp[((size_t)b*4 + 2)*256 + n] + g_bp[((size_t)b*4 + 3)*256 + n];
    }
    float* Y = g_y4 + (size_t)b * PB;
#pragma unroll
    for (int u = 0; u < 8; u++) {
        int m = m0 + (u < 4 ? ty*4 + u : 64 + ty*4 + (u - 4));
        float4 w0 = make_float4(acc[u][0]+bn8[0], acc[u][1]+bn8[1], acc[u][2]+bn8[2], acc[u][3]+bn8[3]);
        float4 w1 = make_float4(acc[u][4]+bn8[4], acc[u][5]+bn8[5], acc[u][6]+bn8[6], acc[u][7]+bn8[7]);
        *reinterpret_cast<float4*>(Y + (size_t)m * 256 + n0 + tx*4)      = w0;
        *reinterpret_cast<float4*>(Y + (size_t)m * 256 + n0 + 64 + tx*4) = w1;
    }
}

// ---------------- K4: out = wW @ y4 + bW + x   (64x64 GEMM tile + residual)
__global__ void __launch_bounds__(256) k4_out(const float* __restrict__ wW,
                                              const float* __restrict__ bW,
                                              const float* __restrict__ x,
                                              float* __restrict__ out) {
    const int p0 = blockIdx.x * 64;
    const int b = blockIdx.y;
    __shared__ float Ws[64][64];   // Ws[k][o] = wW[o][k]
    __shared__ float Ys[64][64];   // Ys[k][p]
    const int t = threadIdx.x;
    for (int idx = t; idx < 4096; idx += 256) {
        int o = idx >> 6, k = idx & 63;
        Ws[k][o] = wW[idx];
    }
    const float* Y = g_y4 + (size_t)b * PB + p0;
    for (int idx = t; idx < 1024; idx += 256) {
        int k = idx >> 4, p4 = (idx & 15) * 4;
        *reinterpret_cast<float4*>(&Ys[k][p4]) =
            *reinterpret_cast<const float4*>(Y + (size_t)k * HWP + p4);
    }
    __syncthreads();

    const int ty = t >> 4, tx = t & 15;
    float acc[4][4];
#pragma unroll
    for (int u = 0; u < 4; u++)
#pragma unroll
        for (int v = 0; v < 4; v++) acc[u][v] = 0.f;

    for (int k = 0; k < 64; k++) {
        float af[4], bf[4];
        *reinterpret_cast<float4*>(af) = *reinterpret_cast<const float4*>(&Ws[k][ty*4]);
        *reinterpret_cast<float4*>(bf) = *reinterpret_cast<const float4*>(&Ys[k][tx*4]);
#pragma unroll
        for (int u = 0; u < 4; u++)
#pragma unroll
            for (int v = 0; v < 4; v++) acc[u][v] = fmaf(af[u], bf[v], acc[u][v]);
    }

#pragma unroll
    for (int u = 0; u < 4; u++) {
        int o = ty * 4 + u;
        size_t base = (size_t)b * PB + (size_t)o * HWP + p0 + tx * 4;
        float4 xr = *reinterpret_cast<const float4*>(x + base);
        float bwo = __ldg(&bW[o]);
        float4 w = make_float4(acc[u][0] + bwo + xr.x, acc[u][1] + bwo + xr.y,
                               acc[u][2] + bwo + xr.z, acc[u][3] + bwo + xr.w);
        *reinterpret_cast<float4*>(out + base) = w;
    }
}

extern "C" void kernel_launch(void* const* d_in, const int* in_sizes, int n_in,
                              void* d_out, int out_size) {
    const float* x    = (const float*)d_in[0];
    const float* ref  = (const float*)d_in[1];
    const float* w_g  = (const float*)d_in[2];
    const float* b_g  = (const float*)d_in[3];
    const float* w_th = (const float*)d_in[4];
    const float* b_th = (const float*)d_in[5];
    const float* w_ph = (const float*)d_in[6];
    const float* b_ph = (const float*)d_in[7];
    const float* w_W  = (const float*)d_in[8];
    const float* b_W  = (const float*)d_in[9];
    float* out = (float*)d_out;

    k0_rowsum  <<<dim3(256, 8, 2),  256>>>(x, ref);
    k1_gram    <<<dim3(4, 8, SPLIT),256>>>(ref, x);
    k2a_f      <<<dim3(16, 8),      256>>>(w_th, b_th, w_ph, b_ph);
    k2b_softmax<<<dim3(32, 8),      256>>>();
    k2c_u      <<<dim3(4, 8),       256>>>(w_g, b_g);
    k3_y       <<<dim3(256, 8),     256>>>(x);
    k4_out     <<<dim3(1024, 8),    256>>>(w_W, b_W, x, out);
}

// round 7
// speedup vs baseline: 1.0003x; 1.0003x over previous
#include <cuda_runtime.h>
#include <cstddef>

#define BATCH 8
#define HWP   65536
#define PB    4194304            // 64*65536 floats per batch
#define KDIM  16384
#define NROW  256
#define SPLIT 32
#define KCH   (KDIM / SPLIT)     // 512

__device__ float g_part[(size_t)SPLIT * BATCH * NROW * NROW];
__device__ float g_sr[BATCH * NROW];
__device__ float g_sx[BATCH * NROW];
__device__ float g_f [BATCH * NROW * NROW];
__device__ float g_U [BATCH * NROW * NROW];
__device__ float g_bp[BATCH * 4 * NROW];
__device__ float g_y4[(size_t)BATCH * PB];

// ------------------------------------------------------------- K0: row sums
__global__ void k0_rowsum(const float* __restrict__ x, const float* __restrict__ ref) {
    int r = blockIdx.x, b = blockIdx.y, which = blockIdx.z;
    const float* src = which ? x : ref;
    const float4* p = reinterpret_cast<const float4*>(src + (size_t)b * PB + (size_t)r * KDIM);
    float s = 0.f;
    for (int i = threadIdx.x; i < KDIM / 4; i += 256) {
        float4 v = p[i];
        s += (v.x + v.y) + (v.z + v.w);
    }
    __shared__ float red[256];
    red[threadIdx.x] = s;
    __syncthreads();
    for (int o = 128; o > 0; o >>= 1) {
        if (threadIdx.x < o) red[threadIdx.x] += red[threadIdx.x + o];
        __syncthreads();
    }
    if (threadIdx.x == 0) (which ? g_sx : g_sr)[b * NROW + r] = red[0];
}

// -------------------------------------------- K1: G = ref2 @ x2^T  (split-K)
__global__ void __launch_bounds__(256) k1_gram(const float* __restrict__ ref,
                                               const float* __restrict__ x) {
    const int ti = blockIdx.x >> 1, tj = blockIdx.x & 1;
    const int b = blockIdx.y, sp = blockIdx.z;
    const float* A  = ref + (size_t)b * PB + (size_t)(ti * 128) * KDIM + sp * KCH;
    const float* Bp = x   + (size_t)b * PB + (size_t)(tj * 128) * KDIM + sp * KCH;

    __shared__ float As[2][8][132];
    __shared__ float Bs[2][8][132];

    const int t  = threadIdx.x;
    const int lr = t >> 1;
    const int lq = (t & 1) * 4;
    const int ty = t >> 4, tx = t & 15;

    float acc[8][8];
#pragma unroll
    for (int u = 0; u < 8; u++)
#pragma unroll
        for (int v = 0; v < 8; v++) acc[u][v] = 0.f;

    float4 av = *reinterpret_cast<const float4*>(A  + (size_t)lr * KDIM + lq);
    float4 bv = *reinterpret_cast<const float4*>(Bp + (size_t)lr * KDIM + lq);
    As[0][lq+0][lr]=av.x; As[0][lq+1][lr]=av.y; As[0][lq+2][lr]=av.z; As[0][lq+3][lr]=av.w;
    Bs[0][lq+0][lr]=bv.x; Bs[0][lq+1][lr]=bv.y; Bs[0][lq+2][lr]=bv.z; Bs[0][lq+3][lr]=bv.w;
    __syncthreads();

    const int NIT = KCH / 8;
    for (int kk = 0; kk < NIT; ++kk) {
        const int cur = kk & 1, nxt = cur ^ 1;
        if (kk + 1 < NIT) {
            av = *reinterpret_cast<const float4*>(A  + (size_t)lr * KDIM + (kk+1)*8 + lq);
            bv = *reinterpret_cast<const float4*>(Bp + (size_t)lr * KDIM + (kk+1)*8 + lq);
        }
#pragma unroll
        for (int k = 0; k < 8; k++) {
            float af[8], bf[8];
            *reinterpret_cast<float4*>(af)     = *reinterpret_cast<const float4*>(&As[cur][k][ty*4]);
            *reinterpret_cast<float4*>(af + 4) = *reinterpret_cast<const float4*>(&As[cur][k][64 + ty*4]);
            *reinterpret_cast<float4*>(bf)     = *reinterpret_cast<const float4*>(&Bs[cur][k][tx*4]);
            *reinterpret_cast<float4*>(bf + 4) = *reinterpret_cast<const float4*>(&Bs[cur][k][64 + tx*4]);
#pragma unroll
            for (int u = 0; u < 8; u++)
#pragma unroll
                for (int v = 0; v < 8; v++) acc[u][v] = fmaf(af[u], bf[v], acc[u][v]);
        }
        if (kk + 1 < NIT) {
            As[nxt][lq+0][lr]=av.x; As[nxt][lq+1][lr]=av.y; As[nxt][lq+2][lr]=av.z; As[nxt][lq+3][lr]=av.w;
            Bs[nxt][lq+0][lr]=bv.x; Bs[nxt][lq+1][lr]=bv.y; Bs[nxt][lq+2][lr]=bv.z; Bs[nxt][lq+3][lr]=bv.w;
        }
        __syncthreads();
    }

    float* outp = g_part + ((size_t)sp * BATCH + b) * ((size_t)NROW * NROW);
#pragma unroll
    for (int u = 0; u < 8; u++) {
        int row = ti * 128 + (u < 4 ? ty*4 + u : 64 + ty*4 + (u - 4));
        float4 w0 = make_float4(acc[u][0], acc[u][1], acc[u][2], acc[u][3]);
        float4 w1 = make_float4(acc[u][4], acc[u][5], acc[u][6], acc[u][7]);
        *reinterpret_cast<float4*>(outp + (size_t)row * NROW + tj*128 + tx*4)      = w0;
        *reinterpret_cast<float4*>(outp + (size_t)row * NROW + tj*128 + 64 + tx*4) = w1;
    }
}

// ---------------- K2a: f = Wth' G Wph'^T + conv-bias rank-1 terms
__global__ void k2a_f(const float* __restrict__ wth, const float* __restrict__ bth,
                      const float* __restrict__ wph, const float* __restrict__ bph) {
    const int hb1 = blockIdx.x >> 2, hb2 = blockIdx.x & 3, b = blockIdx.y;
    __shared__ float S[64][64];
    __shared__ float T[64][64];
    __shared__ float ths[64], phs[64];
    const int t = threadIdx.x;

    for (int idx = t; idx < 4096; idx += 256) {
        int c = idx >> 6, cp = idx & 63;
        size_t off = (size_t)b * 65536 + (size_t)(c*4 + hb1) * 256 + cp*4 + hb2;
        float a = 0.f;
#pragma unroll 8
        for (int s = 0; s < SPLIT; s++) a += g_part[(size_t)s * (BATCH * 65536) + off];
        S[c][cp] = a;
    }
    __syncthreads();

    for (int idx = t; idx < 4096; idx += 256) {
        int ci = idx >> 6, cp = idx & 63;
        float a = 0.f;
#pragma unroll
        for (int c = 0; c < 64; c++) a = fmaf(__ldg(&wth[ci*64 + c]), S[c][cp], a);
        T[ci][cp] = a;
    }
    __syncthreads();

    if (t < 64) {
        float a = 0.f;
        for (int c = 0; c < 64; c++) a = fmaf(wth[t*64 + c], g_sr[b*256 + c*4 + hb1], a);
        ths[t] = a;
    } else if (t < 128) {
        int ci = t - 64;
        float a = 0.f;
        for (int cp = 0; cp < 64; cp++) a = fmaf(wph[ci*64 + cp], g_sx[b*256 + cp*4 + hb2], a);
        phs[ci] = a;
    }
    for (int idx = t; idx < 4096; idx += 256) {
        int ci2 = idx >> 6, cp = idx & 63;
        S[cp][ci2] = wph[idx];
    }
    __syncthreads();

    for (int idx = t; idx < 4096; idx += 256) {
        int ci1 = idx >> 6, ci2 = idx & 63;
        float a = 0.f;
#pragma unroll
        for (int cp = 0; cp < 64; cp++) a = fmaf(T[ci1][cp], S[cp][ci2], a);
        float bt = __ldg(&bth[ci1]), bp = __ldg(&bph[ci2]);
        a += bt * phs[ci2] + ths[ci1] * bp + 16384.f * bt * bp;
        g_f[(size_t)b * 65536 + (size_t)(ci1*4 + hb1) * 256 + ci2*4 + hb2] = a;
    }
}

// ---------------- K2b: softmax over rows (axis=1), per column
__global__ void k2b_softmax() {
    const int b = blockIdx.y;
    const int col = blockIdx.x * 8 + (threadIdx.x >> 5);
    const int lane = threadIdx.x & 31;
    float* F = g_f + (size_t)b * 65536;
    float v[8];
#pragma unroll
    for (int s = 0; s < 8; s++) v[s] = F[(s*32 + lane) * 256 + col];
    float m = v[0];
#pragma unroll
    for (int s = 1; s < 8; s++) m = fmaxf(m, v[s]);
#pragma unroll
    for (int o = 16; o > 0; o >>= 1) m = fmaxf(m, __shfl_xor_sync(0xffffffffu, m, o));
    float sum = 0.f;
#pragma unroll
    for (int s = 0; s < 8; s++) { v[s] = expf(v[s] - m); sum += v[s]; }
#pragma unroll
    for (int o = 16; o > 0; o >>= 1) sum += __shfl_xor_sync(0xffffffffu, sum, o);
    float r = 1.f / sum;
#pragma unroll
    for (int s = 0; s < 8; s++) F[(s*32 + lane) * 256 + col] = v[s] * r;
}

// ---------------- K2c: U = fdiv * Wg-blockdiag, beta partials
__global__ void k2c_u(const float* __restrict__ wg, const float* __restrict__ bg) {
    const int hb2 = blockIdx.x, b = blockIdx.y;
    __shared__ float wgs[64][64];
    for (int idx = threadIdx.x; idx < 4096; idx += 256) wgs[idx >> 6][idx & 63] = wg[idx];
    __syncthreads();
    const int i = threadIdx.x;
    const float* F = g_f + (size_t)b * 65536 + (size_t)i * 256 + hb2;
    float frow[64];
#pragma unroll
    for (int ci = 0; ci < 64; ci++) frow[ci] = F[ci * 4];
    float* U = g_U + (size_t)b * 65536 + (size_t)i * 256 + hb2;
    for (int c = 0; c < 64; c++) {
        float a = 0.f;
#pragma unroll
        for (int ci = 0; ci < 64; ci++) a = fmaf(frow[ci], wgs[ci][c], a);
        U[c * 4] = a;
    }
    float bs = 0.f;
#pragma unroll
    for (int ci = 0; ci < 64; ci++) bs = fmaf(frow[ci], __ldg(&bg[ci]), bs);
    g_bp[((size_t)b * 4 + hb2) * 256 + i] = bs;
}

// ---------------- K3: Y4 = x2^T @ U^T + beta  (lands in NCHW layout)
__global__ void __launch_bounds__(256) k3_y(const float* __restrict__ x) {
    const int nt = blockIdx.x & 1, mt = blockIdx.x >> 1;
    const int b = blockIdx.y;
    const int m0 = mt * 128, n0 = nt * 128;
    const float* xp = x   + (size_t)b * PB;
    const float* Up = g_U + (size_t)b * 65536;

    __shared__ float As[2][8][132];
    __shared__ float Bs[2][8][132];

    const int t = threadIdx.x;
    const int akq = t >> 5, am4 = (t & 31) * 4;
    const int bn = t >> 1, bkq = (t & 1) * 4;
    const int ty = t >> 4, tx = t & 15;

    float acc[8][8];
#pragma unroll
    for (int u = 0; u < 8; u++)
#pragma unroll
        for (int v = 0; v < 8; v++) acc[u][v] = 0.f;

    float4 av = *reinterpret_cast<const float4*>(xp + (size_t)akq * KDIM + m0 + am4);
    float4 bv = *reinterpret_cast<const float4*>(Up + (size_t)(n0 + bn) * 256 + bkq);
    *reinterpret_cast<float4*>(&As[0][akq][am4]) = av;
    Bs[0][bkq+0][bn]=bv.x; Bs[0][bkq+1][bn]=bv.y; Bs[0][bkq+2][bn]=bv.z; Bs[0][bkq+3][bn]=bv.w;
    __syncthreads();

    const int NIT = 256 / 8;
    for (int kk = 0; kk < NIT; ++kk) {
        const int cur = kk & 1, nxt = cur ^ 1;
        if (kk + 1 < NIT) {
            av = *reinterpret_cast<const float4*>(xp + (size_t)((kk+1)*8 + akq) * KDIM + m0 + am4);
            bv = *reinterpret_cast<const float4*>(Up + (size_t)(n0 + bn) * 256 + (kk+1)*8 + bkq);
        }
#pragma unroll
        for (int k = 0; k < 8; k++) {
            float af[8], bf[8];
            *reinterpret_cast<float4*>(af)     = *reinterpret_cast<const float4*>(&As[cur][k][ty*4]);
            *reinterpret_cast<float4*>(af + 4) = *reinterpret_cast<const float4*>(&As[cur][k][64 + ty*4]);
            *reinterpret_cast<float4*>(bf)     = *reinterpret_cast<const float4*>(&Bs[cur][k][tx*4]);
            *reinterpret_cast<float4*>(bf + 4) = *reinterpret_cast<const float4*>(&Bs[cur][k][64 + tx*4]);
#pragma unroll
            for (int u = 0; u < 8; u++)
#pragma unroll
                for (int v = 0; v < 8; v++) acc[u][v] = fmaf(af[u], bf[v], acc[u][v]);
        }
        if (kk + 1 < NIT) {
            *reinterpret_cast<float4*>(&As[nxt][akq][am4]) = av;
            Bs[nxt][bkq+0][bn]=bv.x; Bs[nxt][bkq+1][bn]=bv.y; Bs[nxt][bkq+2][bn]=bv.z; Bs[nxt][bkq+3][bn]=bv.w;
        }
        __syncthreads();
    }

    float bn8[8];
#pragma unroll
    for (int v = 0; v < 8; v++) {
        int n = n0 + (v < 4 ? tx*4 + v : 64 + tx*4 + (v - 4));
        bn8[v] = g_bp[((size_t)b*4 + 0)*256 + n] + g_bp[((size_t)b*4 + 1)*256 + n]
               + g_bp[((size_t)b*4 + 2)*256 + n] + g_bp[((size_t)b*4 + 3)*256 + n];
    }
    float* Y = g_y4 + (size_t)b * PB;
#pragma unroll
    for (int u = 0; u < 8; u++) {
        int m = m0 + (u < 4 ? ty*4 + u : 64 + ty*4 + (u - 4));
        float4 w0 = make_float4(acc[u][0]+bn8[0], acc[u][1]+bn8[1], acc[u][2]+bn8[2], acc[u][3]+bn8[3]);
        float4 w1 = make_float4(acc[u][4]+bn8[4], acc[u][5]+bn8[5], acc[u][6]+bn8[6], acc[u][7]+bn8[7]);
        *reinterpret_cast<float4*>(Y + (size_t)m * 256 + n0 + tx*4)      = w0;
        *reinterpret_cast<float4*>(Y + (size_t)m * 256 + n0 + 64 + tx*4) = w1;
    }
}

// ---------------- K4: out = wW @ y4 + bW + x   (64x64 GEMM tile + residual)
__global__ void __launch_bounds__(256) k4_out(const float* __restrict__ wW,
                                              const float* __restrict__ bW,
                                              const float* __restrict__ x,
                                              float* __restrict__ out) {
    const int p0 = blockIdx.x * 64;
    const int b = blockIdx.y;
    __shared__ float Ws[64][64];   // Ws[k][o] = wW[o][k]
    __shared__ float Ys[64][64];   // Ys[k][p]
    const int t = threadIdx.x;
    for (int idx = t; idx < 4096; idx += 256) {
        int o = idx >> 6, k = idx & 63;
        Ws[k][o] = wW[idx];
    }
    const float* Y = g_y4 + (size_t)b * PB + p0;
    for (int idx = t; idx < 1024; idx += 256) {
        int k = idx >> 4, p4 = (idx & 15) * 4;
        *reinterpret_cast<float4*>(&Ys[k][p4]) =
            *reinterpret_cast<const float4*>(Y + (size_t)k * HWP + p4);
    }
    __syncthreads();

    const int ty = t >> 4, tx = t & 15;
    float acc[4][4];
#pragma unroll
    for (int u = 0; u < 4; u++)
#pragma unroll
        for (int v = 0; v < 4; v++) acc[u][v] = 0.f;

    for (int k = 0; k < 64; k++) {
        float af[4], bf[4];
        *reinterpret_cast<float4*>(af) = *reinterpret_cast<const float4*>(&Ws[k][ty*4]);
        *reinterpret_cast<float4*>(bf) = *reinterpret_cast<const float4*>(&Ys[k][tx*4]);
#pragma unroll
        for (int u = 0; u < 4; u++)
#pragma unroll
            for (int v = 0; v < 4; v++) acc[u][v] = fmaf(af[u], bf[v], acc[u][v]);
    }

#pragma unroll
    for (int u = 0; u < 4; u++) {
        int o = ty * 4 + u;
        size_t base = (size_t)b * PB + (size_t)o * HWP + p0 + tx * 4;
        float4 xr = *reinterpret_cast<const float4*>(x + base);
        float bwo = __ldg(&bW[o]);
        float4 w = make_float4(acc[u][0] + bwo + xr.x, acc[u][1] + bwo + xr.y,
                               acc[u][2] + bwo + xr.z, acc[u][3] + bwo + xr.w);
        *reinterpret_cast<float4*>(out + base) = w;
    }
}

extern "C" void kernel_launch(void* const* d_in, const int* in_sizes, int n_in,
                              void* d_out, int out_size) {
    const float* x    = (const float*)d_in[0];
    const float* ref  = (const float*)d_in[1];
    const float* w_g  = (const float*)d_in[2];
    const float* b_g  = (const float*)d_in[3];
    const float* w_th = (const float*)d_in[4];
    const float* b_th = (const float*)d_in[5];
    const float* w_ph = (const float*)d_in[6];
    const float* b_ph = (const float*)d_in[7];
    const float* w_W  = (const float*)d_in[8];
    const float* b_W  = (const float*)d_in[9];
    float* out = (float*)d_out;

    k0_rowsum  <<<dim3(256, 8, 2),  256>>>(x, ref);
    k1_gram    <<<dim3(4, 8, SPLIT),256>>>(ref, x);
    k2a_f      <<<dim3(16, 8),      256>>>(w_th, b_th, w_ph, b_ph);
    k2b_softmax<<<dim3(32, 8),      256>>>();
    k2c_u      <<<dim3(4, 8),       256>>>(w_g, b_g);
    k3_y       <<<dim3(256, 8),     256>>>(x);
    k4_out     <<<dim3(1024, 8),    256>>>(w_W, b_W, x, out);
}

// round 9
// speedup vs baseline: 1.0699x; 1.0696x over previous
#include <cuda_runtime.h>
#include <cuda_bf16.h>
#include <cstdint>
#include <cstddef>

#define BATCH 8
#define PB    4194304
#define KD    16384
#define SPLIT 8

__device__ float g_part[(size_t)SPLIT * BATCH * 65536];
__device__ float g_sr[BATCH * 256];
__device__ float g_sx[BATCH * 256];
__device__ float g_f [BATCH * 65536];
__device__ __nv_bfloat16 g_Uh[BATCH * 65536];
__device__ __nv_bfloat16 g_Ue[BATCH * 65536];
__device__ float g_bp[BATCH * 4 * 256];
__device__ float g_y4[(size_t)BATCH * PB];

static __device__ __forceinline__ void hmma(float* d, const uint32_t* a, const uint32_t* b) {
    asm volatile("mma.sync.aligned.m16n8k16.row.col.f32.bf16.bf16.f32 "
        "{%0,%1,%2,%3}, {%4,%5,%6,%7}, {%8,%9}, {%0,%1,%2,%3};"
        : "+f"(d[0]), "+f"(d[1]), "+f"(d[2]), "+f"(d[3])
        : "r"(a[0]), "r"(a[1]), "r"(a[2]), "r"(a[3]), "r"(b[0]), "r"(b[1]));
}
// pack (x,y) -> bf16x2 hi plane + bf16x2 residual plane
static __device__ __forceinline__ void pk(float x, float y, uint32_t& h, uint32_t& e) {
    uint32_t hv;
    asm("cvt.rn.bf16x2.f32 %0, %1, %2;" : "=r"(hv) : "f"(y), "f"(x));
    float hx = __uint_as_float(hv << 16);
    float hy = __uint_as_float(hv & 0xFFFF0000u);
    float ex = x - hx, ey = y - hy;
    uint32_t ev;
    asm("cvt.rn.bf16x2.f32 %0, %1, %2;" : "=r"(ev) : "f"(ey), "f"(ex));
    h = hv; e = ev;
}

__global__ void kz() {
    int i = blockIdx.x * 256 + threadIdx.x;
    g_sr[i] = 0.f; g_sx[i] = 0.f;
}

// ---- K1: G = ref2 @ x2^T, HMMA, hi/lo split, split-K, fused rowsums ----
// smem planes (u32 view, row stride 36 u32 = 72 bf16): AH 0, AE 4608, BH 9216, BE 13824
__global__ void __launch_bounds__(256) k1(const float* __restrict__ ref, const float* __restrict__ x) {
    extern __shared__ uint32_t smu[];
    uint32_t* pAH = smu;         uint32_t* pAE = smu + 4608;
    uint32_t* pBH = smu + 9216;  uint32_t* pBE = smu + 13824;
    const int t = threadIdx.x, lane = t & 31, wid = t >> 5;
    const int wm = wid >> 2, wn = wid & 3, g = lane >> 2, tg = lane & 3;
    const int mt_ = blockIdx.x >> 1, nt_ = blockIdx.x & 1, b = blockIdx.y, sp = blockIdx.z;
    const int m0 = mt_ * 128, n0 = nt_ * 128;
    const float* Ag = ref + (size_t)b * PB + (size_t)m0 * KD + sp * 2048;
    const float* Bg = x   + (size_t)b * PB + (size_t)n0 * KD + sp * 2048;
    const int r = t >> 1, kb = (t & 1) * 32;
    float sa = 0.f, sx = 0.f;
    float acc[4][4][4];
#pragma unroll
    for (int i = 0; i < 4; i++)
#pragma unroll
        for (int j = 0; j < 4; j++)
#pragma unroll
            for (int q = 0; q < 4; q++) acc[i][j][q] = 0.f;

    for (int ck = 0; ck < 32; ck++) {
        const float4* ap = (const float4*)(Ag + (size_t)r * KD + ck * 64 + kb);
        float4 va[8];
#pragma unroll
        for (int q = 0; q < 8; q++) va[q] = ap[q];
        __syncthreads();
#pragma unroll
        for (int q = 0; q < 8; q++) {
            sa += (va[q].x + va[q].y) + (va[q].z + va[q].w);
            uint32_t h0, e0, h1, e1;
            pk(va[q].x, va[q].y, h0, e0); pk(va[q].z, va[q].w, h1, e1);
            int ix = r * 36 + ((kb + q * 4) >> 1);
            pAH[ix] = h0; pAH[ix + 1] = h1; pAE[ix] = e0; pAE[ix + 1] = e1;
        }
        const float4* bp = (const float4*)(Bg + (size_t)r * KD + ck * 64 + kb);
        float4 vb[8];
#pragma unroll
        for (int q = 0; q < 8; q++) vb[q] = bp[q];
#pragma unroll
        for (int q = 0; q < 8; q++) {
            sx += (vb[q].x + vb[q].y) + (vb[q].z + vb[q].w);
            uint32_t h0, e0, h1, e1;
            pk(vb[q].x, vb[q].y, h0, e0); pk(vb[q].z, vb[q].w, h1, e1);
            int ix = r * 36 + ((kb + q * 4) >> 1);
            pBH[ix] = h0; pBH[ix + 1] = h1; pBE[ix] = e0; pBE[ix + 1] = e1;
        }
        __syncthreads();
#pragma unroll
        for (int kk = 0; kk < 4; kk++) {
            const int kh = kk * 8;  // k0/2
            uint32_t Ah[4][4], Ae[4][4], Bh[4][2], Be[4][2];
#pragma unroll
            for (int mt = 0; mt < 4; mt++) {
                int mr = wm * 64 + mt * 16;
                Ah[mt][0] = pAH[(mr + g) * 36 + kh + tg];
                Ah[mt][1] = pAH[(mr + g + 8) * 36 + kh + tg];
                Ah[mt][2] = pAH[(mr + g) * 36 + kh + tg + 4];
                Ah[mt][3] = pAH[(mr + g + 8) * 36 + kh + tg + 4];
                Ae[mt][0] = pAE[(mr + g) * 36 + kh + tg];
                Ae[mt][1] = pAE[(mr + g + 8) * 36 + kh + tg];
                Ae[mt][2] = pAE[(mr + g) * 36 + kh + tg + 4];
                Ae[mt][3] = pAE[(mr + g + 8) * 36 + kh + tg + 4];
            }
#pragma unroll
            for (int nt = 0; nt < 4; nt++) {
                int nr = wn * 32 + nt * 8 + g;
                Bh[nt][0] = pBH[nr * 36 + kh + tg];
                Bh[nt][1] = pBH[nr * 36 + kh + tg + 4];
                Be[nt][0] = pBE[nr * 36 + kh + tg];
                Be[nt][1] = pBE[nr * 36 + kh + tg + 4];
            }
#pragma unroll
            for (int mt = 0; mt < 4; mt++)
#pragma unroll
                for (int nt = 0; nt < 4; nt++) {
                    hmma(acc[mt][nt], Ah[mt], Bh[nt]);
                    hmma(acc[mt][nt], Ah[mt], Be[nt]);
                    hmma(acc[mt][nt], Ae[mt], Bh[nt]);
                }
        }
    }
    sa += __shfl_xor_sync(0xffffffffu, sa, 1);
    sx += __shfl_xor_sync(0xffffffffu, sx, 1);
    if ((t & 1) == 0) {
        if (nt_ == 0) atomicAdd(&g_sr[b * 256 + m0 + r], sa);
        if (mt_ == 0) atomicAdd(&g_sx[b * 256 + n0 + r], sx);
    }
    float* op = g_part + ((size_t)sp * BATCH + b) * 65536;
#pragma unroll
    for (int mt = 0; mt < 4; mt++)
#pragma unroll
        for (int nt = 0; nt < 4; nt++) {
            int row = m0 + wm * 64 + mt * 16 + g;
            int col = n0 + wn * 32 + nt * 8 + tg * 2;
            *(float2*)(op + (size_t)row * 256 + col) = make_float2(acc[mt][nt][0], acc[mt][nt][1]);
            *(float2*)(op + (size_t)(row + 8) * 256 + col) = make_float2(acc[mt][nt][2], acc[mt][nt][3]);
        }
}

// ---- K2a: f = Wth' G Wph'^T + bias rank-1 (reduces split-K partials) ----
__global__ void k2a_f(const float* __restrict__ wth, const float* __restrict__ bth,
                      const float* __restrict__ wph, const float* __restrict__ bph) {
    const int hb1 = blockIdx.x >> 2, hb2 = blockIdx.x & 3, b = blockIdx.y;
    __shared__ float S[64][64], T[64][64], ths[64], phs[64];
    const int t = threadIdx.x;
    for (int idx = t; idx < 4096; idx += 256) {
        int c = idx >> 6, cp = idx & 63;
        size_t off = (size_t)b * 65536 + (size_t)(c * 4 + hb1) * 256 + cp * 4 + hb2;
        float a = 0.f;
#pragma unroll
        for (int s = 0; s < SPLIT; s++) a += g_part[(size_t)s * (BATCH * 65536) + off];
        S[c][cp] = a;
    }
    __syncthreads();
    for (int idx = t; idx < 4096; idx += 256) {
        int ci = idx >> 6, cp = idx & 63;
        float a = 0.f;
#pragma unroll
        for (int c = 0; c < 64; c++) a = fmaf(__ldg(&wth[ci * 64 + c]), S[c][cp], a);
        T[ci][cp] = a;
    }
    __syncthreads();
    if (t < 64) {
        float a = 0.f;
        for (int c = 0; c < 64; c++) a = fmaf(wth[t * 64 + c], g_sr[b * 256 + c * 4 + hb1], a);
        ths[t] = a;
    } else if (t < 128) {
        int ci = t - 64;
        float a = 0.f;
        for (int cp = 0; cp < 64; cp++) a = fmaf(wph[ci * 64 + cp], g_sx[b * 256 + cp * 4 + hb2], a);
        phs[ci] = a;
    }
    for (int idx = t; idx < 4096; idx += 256) S[idx & 63][idx >> 6] = wph[idx];
    __syncthreads();
    for (int idx = t; idx < 4096; idx += 256) {
        int c1 = idx >> 6, c2 = idx & 63;
        float a = 0.f;
#pragma unroll
        for (int cp = 0; cp < 64; cp++) a = fmaf(T[c1][cp], S[cp][c2], a);
        float bt = __ldg(&bth[c1]), bp = __ldg(&bph[c2]);
        a += bt * phs[c2] + ths[c1] * bp + 16384.f * bt * bp;
        g_f[(size_t)b * 65536 + (size_t)(c1 * 4 + hb1) * 256 + c2 * 4 + hb2] = a;
    }
}

__global__ void k2b_softmax() {
    const int b = blockIdx.y, col = blockIdx.x * 8 + (threadIdx.x >> 5), lane = threadIdx.x & 31;
    float* F = g_f + (size_t)b * 65536;
    float v[8];
#pragma unroll
    for (int s = 0; s < 8; s++) v[s] = F[(s * 32 + lane) * 256 + col];
    float m = v[0];
#pragma unroll
    for (int s = 1; s < 8; s++) m = fmaxf(m, v[s]);
#pragma unroll
    for (int o = 16; o > 0; o >>= 1) m = fmaxf(m, __shfl_xor_sync(0xffffffffu, m, o));
    float sum = 0.f;
#pragma unroll
    for (int s = 0; s < 8; s++) { v[s] = expf(v[s] - m); sum += v[s]; }
#pragma unroll
    for (int o = 16; o > 0; o >>= 1) sum += __shfl_xor_sync(0xffffffffu, sum, o);
    float rcp = 1.f / sum;
#pragma unroll
    for (int s = 0; s < 8; s++) F[(s * 32 + lane) * 256 + col] = v[s] * rcp;
}

// ---- K2c: U = fdiv * Wg-blockdiag (bf16 hi/lo planes), beta partials ----
__global__ void k2c_u(const float* __restrict__ wg, const float* __restrict__ bg) {
    const int hb2 = blockIdx.x, b = blockIdx.y;
    __shared__ float wgs[64][64];
    for (int idx = threadIdx.x; idx < 4096; idx += 256) wgs[idx >> 6][idx & 63] = wg[idx];
    __syncthreads();
    const int i = threadIdx.x;
    const float* F = g_f + (size_t)b * 65536 + (size_t)i * 256 + hb2;
    float fr[64];
#pragma unroll
    for (int ci = 0; ci < 64; ci++) fr[ci] = F[ci * 4];
    __nv_bfloat16* Uh = g_Uh + (size_t)b * 65536 + (size_t)i * 256 + hb2;
    __nv_bfloat16* Ue = g_Ue + (size_t)b * 65536 + (size_t)i * 256 + hb2;
    for (int c = 0; c < 64; c++) {
        float a = 0.f;
#pragma unroll
        for (int ci = 0; ci < 64; ci++) a = fmaf(fr[ci], wgs[ci][c], a);
        __nv_bfloat16 h = __float2bfloat16(a);
        Uh[c * 4] = h;
        Ue[c * 4] = __float2bfloat16(a - __bfloat162float(h));
    }
    float bs = 0.f;
#pragma unroll
    for (int ci = 0; ci < 64; ci++) bs = fmaf(fr[ci], __ldg(&bg[ci]), bs);
    g_bp[((size_t)b * 4 + hb2) * 256 + i] = bs;
}

// ---- K3: Y4[f,i] = sum_m x2[m,f] * U[i,m] + beta[i], HMMA hi/lo ----
// smem: AH u32[4608] @0, AE @4608, beta f32[128] @9216
__global__ void __launch_bounds__(256) k3(const float* __restrict__ x) {
    extern __shared__ uint32_t smu[];
    uint32_t* pAH = smu; uint32_t* pAE = smu + 4608;
    float* sbeta = (float*)(smu + 9216);
    const int t = threadIdx.x, lane = t & 31, wid = t >> 5;
    const int wf = wid >> 2, wi = wid & 3, g = lane >> 2, tg = lane & 3;
    const int f0 = (blockIdx.x >> 1) * 128, i0 = (blockIdx.x & 1) * 128, b = blockIdx.y;
    const float* xp = x + (size_t)b * PB;
    const __nv_bfloat16* Uhp = g_Uh + (size_t)b * 65536;
    const __nv_bfloat16* Uep = g_Ue + (size_t)b * 65536;
    if (t < 128) {
        int i = i0 + t;
        sbeta[t] = g_bp[((size_t)b * 4 + 0) * 256 + i] + g_bp[((size_t)b * 4 + 1) * 256 + i]
                 + g_bp[((size_t)b * 4 + 2) * 256 + i] + g_bp[((size_t)b * 4 + 3) * 256 + i];
    }
    const int kr = t >> 2, fq = (t & 3) * 32;
    float acc[4][4][4];
#pragma unroll
    for (int i = 0; i < 4; i++)
#pragma unroll
        for (int j = 0; j < 4; j++)
#pragma unroll
            for (int q = 0; q < 4; q++) acc[i][j][q] = 0.f;

    for (int ck = 0; ck < 4; ck++) {
        const float4* src = (const float4*)(xp + (size_t)(ck * 64 + kr) * KD + f0 + fq);
        float4 v[8];
#pragma unroll
        for (int q = 0; q < 8; q++) v[q] = src[q];
        __syncthreads();
#pragma unroll
        for (int q = 0; q < 8; q++) {
#pragma unroll
            for (int j = 0; j < 4; j++) {
                float val = (&v[q].x)[j];
                __nv_bfloat16 hb = __float2bfloat16(val);
                __nv_bfloat16 eb = __float2bfloat16(val - __bfloat162float(hb));
                int f = fq + q * 4 + j;
                ((__nv_bfloat16*)pAH)[f * 72 + kr] = hb;
                ((__nv_bfloat16*)pAE)[f * 72 + kr] = eb;
            }
        }
        __syncthreads();
#pragma unroll
        for (int kk = 0; kk < 4; kk++) {
            const int kh = kk * 8;
            const int kg = ck * 64 + kk * 16 + tg * 2;
            uint32_t Ah[4][4], Ae[4][4], Bh[4][2], Be[4][2];
#pragma unroll
            for (int mt = 0; mt < 4; mt++) {
                int mr = wf * 64 + mt * 16;
                Ah[mt][0] = pAH[(mr + g) * 36 + kh + tg];
                Ah[mt][1] = pAH[(mr + g + 8) * 36 + kh + tg];
                Ah[mt][2] = pAH[(mr + g) * 36 + kh + tg + 4];
                Ah[mt][3] = pAH[(mr + g + 8) * 36 + kh + tg + 4];
                Ae[mt][0] = pAE[(mr + g) * 36 + kh + tg];
                Ae[mt][1] = pAE[(mr + g + 8) * 36 + kh + tg];
                Ae[mt][2] = pAE[(mr + g) * 36 + kh + tg + 4];
                Ae[mt][3] = pAE[(mr + g + 8) * 36 + kh + tg + 4];
            }
#pragma unroll
            for (int nt = 0; nt < 4; nt++) {
                int i = i0 + wi * 32 + nt * 8 + g;
                Bh[nt][0] = *(const uint32_t*)(Uhp + (size_t)i * 256 + kg);
                Bh[nt][1] = *(const uint32_t*)(Uhp + (size_t)i * 256 + kg + 8);
                Be[nt][0] = *(const uint32_t*)(Uep + (size_t)i * 256 + kg);
                Be[nt][1] = *(const uint32_t*)(Uep + (size_t)i * 256 + kg + 8);
            }
#pragma unroll
            for (int mt = 0; mt < 4; mt++)
#pragma unroll
                for (int nt = 0; nt < 4; nt++) {
                    hmma(acc[mt][nt], Ah[mt], Bh[nt]);
                    hmma(acc[mt][nt], Ah[mt], Be[nt]);
                    hmma(acc[mt][nt], Ae[mt], Bh[nt]);
                }
        }
    }
    float* Y = g_y4 + (size_t)b * PB;
#pragma unroll
    for (int mt = 0; mt < 4; mt++)
#pragma unroll
        for (int nt = 0; nt < 4; nt++) {
            int f = f0 + wf * 64 + mt * 16 + g;
            int il = wi * 32 + nt * 8 + tg * 2;
            float b0 = sbeta[il], b1 = sbeta[il + 1];
            int i = i0 + il;
            *(float2*)(Y + (size_t)f * 256 + i) = make_float2(acc[mt][nt][0] + b0, acc[mt][nt][1] + b1);
            *(float2*)(Y + (size_t)(f + 8) * 256 + i) = make_float2(acc[mt][nt][2] + b0, acc[mt][nt][3] + b1);
        }
}

// ---- K4: out = wW @ y4 + bW + x ----
__global__ void __launch_bounds__(256) k4(const float* __restrict__ wW, const float* __restrict__ bW,
                                          const float* __restrict__ x, float* __restrict__ out) {
    const int p0 = blockIdx.x * 64, b = blockIdx.y;
    __shared__ float Ws[64][64], Ys[64][64];
    const int t = threadIdx.x;
    for (int idx = t; idx < 4096; idx += 256) Ws[idx & 63][idx >> 6] = wW[idx];
    const float* Y = g_y4 + (size_t)b * PB + p0;
    for (int idx = t; idx < 1024; idx += 256) {
        int k = idx >> 4, p4 = (idx & 15) * 4;
        *(float4*)(&Ys[k][p4]) = *(const float4*)(Y + (size_t)k * 65536 + p4);
    }
    __syncthreads();
    const int ty = t >> 4, tx = t & 15;
    float acc[4][4];
#pragma unroll
    for (int u = 0; u < 4; u++)
#pragma unroll
        for (int v = 0; v < 4; v++) acc[u][v] = 0.f;
    for (int k = 0; k < 64; k++) {
        float af[4], bf[4];
        *(float4*)af = *(const float4*)(&Ws[k][ty * 4]);
        *(float4*)bf = *(const float4*)(&Ys[k][tx * 4]);
#pragma unroll
        for (int u = 0; u < 4; u++)
#pragma unroll
            for (int v = 0; v < 4; v++) acc[u][v] = fmaf(af[u], bf[v], acc[u][v]);
    }
#pragma unroll
    for (int u = 0; u < 4; u++) {
        int o = ty * 4 + u;
        size_t base = (size_t)b * PB + (size_t)o * 65536 + p0 + tx * 4;
        float4 xr = *(const float4*)(x + base);
        float bw = __ldg(&bW[o]);
        float4 w = make_float4(acc[u][0] + bw + xr.x, acc[u][1] + bw + xr.y,
                               acc[u][2] + bw + xr.z, acc[u][3] + bw + xr.w);
        *(float4*)(out + base) = w;
    }
}

extern "C" void kernel_launch(void* const* d_in, const int* in_sizes, int n_in,
                              void* d_out, int out_size) {
    const float* x    = (const float*)d_in[0];
    const float* ref  = (const float*)d_in[1];
    const float* w_g  = (const float*)d_in[2];
    const float* b_g  = (const float*)d_in[3];
    const float* w_th = (const float*)d_in[4];
    const float* b_th = (const float*)d_in[5];
    const float* w_ph = (const float*)d_in[6];
    const float* b_ph = (const float*)d_in[7];
    const float* w_W  = (const float*)d_in[8];
    const float* b_W  = (const float*)d_in[9];
    float* out = (float*)d_out;

    cudaFuncSetAttribute(k1, cudaFuncAttributeMaxDynamicSharedMemorySize, 73728);
    cudaFuncSetAttribute(k3, cudaFuncAttributeMaxDynamicSharedMemorySize, 37376);

    kz         <<<8, 256>>>();
    k1         <<<dim3(4, 8, SPLIT), 256, 73728>>>(ref, x);
    k2a_f      <<<dim3(16, 8), 256>>>(w_th, b_th, w_ph, b_ph);
    k2b_softmax<<<dim3(32, 8), 256>>>();
    k2c_u      <<<dim3(4, 8), 256>>>(w_g, b_g);
    k3         <<<dim3(256, 8), 256, 37376>>>(x);
    k4         <<<dim3(1024, 8), 256>>>(w_W, b_W, x, out);
}

// round 10
// speedup vs baseline: 1.3761x; 1.2861x over previous
#include <cuda_runtime.h>
#include <cuda_bf16.h>
#include <cuda_fp16.h>
#include <cstdint>
#include <cstddef>

#define BATCH 8
#define PB    4194304
#define KD    16384
#define SPLIT 8

__device__ float g_part[(size_t)SPLIT * BATCH * 65536];
__device__ float g_sr[BATCH * 256];
__device__ float g_sx[BATCH * 256];
__device__ float g_f [BATCH * 65536];
__device__ __half g_Uh[BATCH * 65536];
__device__ float g_bp[BATCH * 4 * 256];
__device__ float g_y4[(size_t)BATCH * PB];

static __device__ __forceinline__ void hmma_bf(float* d, const uint32_t* a, const uint32_t* b) {
    asm volatile("mma.sync.aligned.m16n8k16.row.col.f32.bf16.bf16.f32 "
        "{%0,%1,%2,%3}, {%4,%5,%6,%7}, {%8,%9}, {%0,%1,%2,%3};"
        : "+f"(d[0]), "+f"(d[1]), "+f"(d[2]), "+f"(d[3])
        : "r"(a[0]), "r"(a[1]), "r"(a[2]), "r"(a[3]), "r"(b[0]), "r"(b[1]));
}
static __device__ __forceinline__ void hmma_hf(float* d, const uint32_t* a, const uint32_t* b) {
    asm volatile("mma.sync.aligned.m16n8k16.row.col.f32.f16.f16.f32 "
        "{%0,%1,%2,%3}, {%4,%5,%6,%7}, {%8,%9}, {%0,%1,%2,%3};"
        : "+f"(d[0]), "+f"(d[1]), "+f"(d[2]), "+f"(d[3])
        : "r"(a[0]), "r"(a[1]), "r"(a[2]), "r"(a[3]), "r"(b[0]), "r"(b[1]));
}
static __device__ __forceinline__ void pk(float x, float y, uint32_t& h, uint32_t& e) {
    uint32_t hv;
    asm("cvt.rn.bf16x2.f32 %0, %1, %2;" : "=r"(hv) : "f"(y), "f"(x));
    float hx = __uint_as_float(hv << 16);
    float hy = __uint_as_float(hv & 0xFFFF0000u);
    uint32_t ev;
    float ex = x - hx, ey = y - hy;
    asm("cvt.rn.bf16x2.f32 %0, %1, %2;" : "=r"(ev) : "f"(ey), "f"(ex));
    h = hv; e = ev;
}

__global__ void kz() {
    int i = blockIdx.x * 256 + threadIdx.x;
    g_sr[i] = 0.f; g_sx[i] = 0.f;
}

// ---- K1: G = ref2 @ x2^T, bf16 3-product, split-K, fused rowsums ----
__global__ void __launch_bounds__(256, 2) k1(const float* __restrict__ ref, const float* __restrict__ x) {
    extern __shared__ uint32_t smu[];
    uint32_t* pAH = smu;         uint32_t* pAE = smu + 4608;
    uint32_t* pBH = smu + 9216;  uint32_t* pBE = smu + 13824;
    const int t = threadIdx.x, lane = t & 31, wid = t >> 5;
    const int wm = wid >> 2, wn = wid & 3, g = lane >> 2, tg = lane & 3;
    const int mt_ = blockIdx.x >> 1, nt_ = blockIdx.x & 1, b = blockIdx.y, sp = blockIdx.z;
    const int m0 = mt_ * 128, n0 = nt_ * 128;
    const float* Ag = ref + (size_t)b * PB + (size_t)m0 * KD + sp * 2048;
    const float* Bg = x   + (size_t)b * PB + (size_t)n0 * KD + sp * 2048;
    const int r = t >> 1, kb = (t & 1) * 32;
    float sa = 0.f, sx = 0.f;
    float acc[4][4][4];
#pragma unroll
    for (int i = 0; i < 4; i++)
#pragma unroll
        for (int j = 0; j < 4; j++)
#pragma unroll
            for (int q = 0; q < 4; q++) acc[i][j][q] = 0.f;

    for (int ck = 0; ck < 32; ck++) {
        const float4* ap = (const float4*)(Ag + (size_t)r * KD + ck * 64 + kb);
        const float4* bp = (const float4*)(Bg + (size_t)r * KD + ck * 64 + kb);
        float4 va[8], vb[8];
#pragma unroll
        for (int q = 0; q < 8; q++) { va[q] = ap[q]; vb[q] = bp[q]; }
        __syncthreads();
#pragma unroll
        for (int q = 0; q < 8; q++) {
            sa += (va[q].x + va[q].y) + (va[q].z + va[q].w);
            sx += (vb[q].x + vb[q].y) + (vb[q].z + vb[q].w);
            uint32_t h0, e0, h1, e1;
            int ix = r * 36 + ((kb + q * 4) >> 1);
            pk(va[q].x, va[q].y, h0, e0); pk(va[q].z, va[q].w, h1, e1);
            pAH[ix] = h0; pAH[ix + 1] = h1; pAE[ix] = e0; pAE[ix + 1] = e1;
            pk(vb[q].x, vb[q].y, h0, e0); pk(vb[q].z, vb[q].w, h1, e1);
            pBH[ix] = h0; pBH[ix + 1] = h1; pBE[ix] = e0; pBE[ix + 1] = e1;
        }
        __syncthreads();
#pragma unroll
        for (int kk = 0; kk < 4; kk++) {
            const int kh = kk * 8;
            uint32_t Ah[4][4], Ae[4][4], Bh[4][2], Be[4][2];
#pragma unroll
            for (int mt = 0; mt < 4; mt++) {
                int mr = wm * 64 + mt * 16;
                Ah[mt][0] = pAH[(mr + g) * 36 + kh + tg];
                Ah[mt][1] = pAH[(mr + g + 8) * 36 + kh + tg];
                Ah[mt][2] = pAH[(mr + g) * 36 + kh + tg + 4];
                Ah[mt][3] = pAH[(mr + g + 8) * 36 + kh + tg + 4];
                Ae[mt][0] = pAE[(mr + g) * 36 + kh + tg];
                Ae[mt][1] = pAE[(mr + g + 8) * 36 + kh + tg];
                Ae[mt][2] = pAE[(mr + g) * 36 + kh + tg + 4];
                Ae[mt][3] = pAE[(mr + g + 8) * 36 + kh + tg + 4];
            }
#pragma unroll
            for (int nt = 0; nt < 4; nt++) {
                int nr = wn * 32 + nt * 8 + g;
                Bh[nt][0] = pBH[nr * 36 + kh + tg];
                Bh[nt][1] = pBH[nr * 36 + kh + tg + 4];
                Be[nt][0] = pBE[nr * 36 + kh + tg];
                Be[nt][1] = pBE[nr * 36 + kh + tg + 4];
            }
#pragma unroll
            for (int mt = 0; mt < 4; mt++)
#pragma unroll
                for (int nt = 0; nt < 4; nt++) {
                    hmma_bf(acc[mt][nt], Ah[mt], Bh[nt]);
                    hmma_bf(acc[mt][nt], Ah[mt], Be[nt]);
                    hmma_bf(acc[mt][nt], Ae[mt], Bh[nt]);
                }
        }
    }
    sa += __shfl_xor_sync(0xffffffffu, sa, 1);
    sx += __shfl_xor_sync(0xffffffffu, sx, 1);
    if ((t & 1) == 0) {
        if (nt_ == 0) atomicAdd(&g_sr[b * 256 + m0 + r], sa);
        if (mt_ == 0) atomicAdd(&g_sx[b * 256 + n0 + r], sx);
    }
    float* op = g_part + ((size_t)sp * BATCH + b) * 65536;
#pragma unroll
    for (int mt = 0; mt < 4; mt++)
#pragma unroll
        for (int nt = 0; nt < 4; nt++) {
            int row = m0 + wm * 64 + mt * 16 + g;
            int col = n0 + wn * 32 + nt * 8 + tg * 2;
            *(float2*)(op + (size_t)row * 256 + col) = make_float2(acc[mt][nt][0], acc[mt][nt][1]);
            *(float2*)(op + (size_t)(row + 8) * 256 + col) = make_float2(acc[mt][nt][2], acc[mt][nt][3]);
        }
}

// ---- K2a: f = Wth' G Wph'^T + bias rank-1 ----
__global__ void k2a_f(const float* __restrict__ wth, const float* __restrict__ bth,
                      const float* __restrict__ wph, const float* __restrict__ bph) {
    const int hb1 = blockIdx.x >> 2, hb2 = blockIdx.x & 3, b = blockIdx.y;
    __shared__ float S[64][64], T[64][64], ths[64], phs[64];
    const int t = threadIdx.x;
    for (int idx = t; idx < 4096; idx += 256) {
        int c = idx >> 6, cp = idx & 63;
        size_t off = (size_t)b * 65536 + (size_t)(c * 4 + hb1) * 256 + cp * 4 + hb2;
        float a = 0.f;
#pragma unroll
        for (int s = 0; s < SPLIT; s++) a += g_part[(size_t)s * (BATCH * 65536) + off];
        S[c][cp] = a;
    }
    __syncthreads();
    for (int idx = t; idx < 4096; idx += 256) {
        int ci = idx >> 6, cp = idx & 63;
        float a = 0.f;
#pragma unroll
        for (int c = 0; c < 64; c++) a = fmaf(__ldg(&wth[ci * 64 + c]), S[c][cp], a);
        T[ci][cp] = a;
    }
    __syncthreads();
    if (t < 64) {
        float a = 0.f;
        for (int c = 0; c < 64; c++) a = fmaf(wth[t * 64 + c], g_sr[b * 256 + c * 4 + hb1], a);
        ths[t] = a;
    } else if (t < 128) {
        int ci = t - 64;
        float a = 0.f;
        for (int cp = 0; cp < 64; cp++) a = fmaf(wph[ci * 64 + cp], g_sx[b * 256 + cp * 4 + hb2], a);
        phs[ci] = a;
    }
    for (int idx = t; idx < 4096; idx += 256) S[idx & 63][idx >> 6] = wph[idx];
    __syncthreads();
    for (int idx = t; idx < 4096; idx += 256) {
        int c1 = idx >> 6, c2 = idx & 63;
        float a = 0.f;
#pragma unroll
        for (int cp = 0; cp < 64; cp++) a = fmaf(T[c1][cp], S[cp][c2], a);
        float bt = __ldg(&bth[c1]), bp = __ldg(&bph[c2]);
        a += bt * phs[c2] + ths[c1] * bp + 16384.f * bt * bp;
        g_f[(size_t)b * 65536 + (size_t)(c1 * 4 + hb1) * 256 + c2 * 4 + hb2] = a;
    }
}

__global__ void k2b_softmax() {
    const int b = blockIdx.y, col = blockIdx.x * 8 + (threadIdx.x >> 5), lane = threadIdx.x & 31;
    float* F = g_f + (size_t)b * 65536;
    float v[8];
#pragma unroll
    for (int s = 0; s < 8; s++) v[s] = F[(s * 32 + lane) * 256 + col];
    float m = v[0];
#pragma unroll
    for (int s = 1; s < 8; s++) m = fmaxf(m, v[s]);
#pragma unroll
    for (int o = 16; o > 0; o >>= 1) m = fmaxf(m, __shfl_xor_sync(0xffffffffu, m, o));
    float sum = 0.f;
#pragma unroll
    for (int s = 0; s < 8; s++) { v[s] = expf(v[s] - m); sum += v[s]; }
#pragma unroll
    for (int o = 16; o > 0; o >>= 1) sum += __shfl_xor_sync(0xffffffffu, sum, o);
    float rcp = 1.f / sum;
#pragma unroll
    for (int s = 0; s < 8; s++) F[(s * 32 + lane) * 256 + col] = v[s] * rcp;
}

// ---- K2c: U = fdiv * Wg-blockdiag -> single fp16 plane; beta partials ----
__global__ void k2c_u(const float* __restrict__ wg, const float* __restrict__ bg) {
    const int hb2 = blockIdx.x, b = blockIdx.y;
    __shared__ float wgs[64][64];
    for (int idx = threadIdx.x; idx < 4096; idx += 256) wgs[idx >> 6][idx & 63] = wg[idx];
    __syncthreads();
    const int i = threadIdx.x;
    const float* F = g_f + (size_t)b * 65536 + (size_t)i * 256 + hb2;
    float fr[64];
#pragma unroll
    for (int ci = 0; ci < 64; ci++) fr[ci] = F[ci * 4];
    __half* Uh = g_Uh + (size_t)b * 65536 + (size_t)i * 256 + hb2;
    for (int c = 0; c < 64; c++) {
        float a = 0.f;
#pragma unroll
        for (int ci = 0; ci < 64; ci++) a = fmaf(fr[ci], wgs[ci][c], a);
        Uh[c * 4] = __float2half(a);
    }
    float bs = 0.f;
#pragma unroll
    for (int ci = 0; ci < 64; ci++) bs = fmaf(fr[ci], __ldg(&bg[ci]), bs);
    g_bp[((size_t)b * 4 + hb2) * 256 + i] = bs;
}

// ---- K3: Y4[f,i] = sum_m x2[m,f]*U[i,m] + beta[i], single-product fp16 ----
__global__ void __launch_bounds__(256) k3(const float* __restrict__ x) {
    extern __shared__ uint32_t smu[];
    uint32_t* pAH = smu;                  // [128 f][36 u32]
    float* sbeta = (float*)(smu + 4608);  // [128]
    const int t = threadIdx.x, lane = t & 31, wid = t >> 5;
    const int wf = wid >> 2, wi = wid & 3, g = lane >> 2, tg = lane & 3;
    const int f0 = (blockIdx.x >> 1) * 128, i0 = (blockIdx.x & 1) * 128, b = blockIdx.y;
    const float* xp = x + (size_t)b * PB;
    const __half* Uhp = g_Uh + (size_t)b * 65536;
    if (t < 128) {
        int i = i0 + t;
        sbeta[t] = g_bp[((size_t)b * 4 + 0) * 256 + i] + g_bp[((size_t)b * 4 + 1) * 256 + i]
                 + g_bp[((size_t)b * 4 + 2) * 256 + i] + g_bp[((size_t)b * 4 + 3) * 256 + i];
    }
    const int kr = t >> 2, fq = (t & 3) * 32;
    float acc[4][4][4];
#pragma unroll
    for (int i = 0; i < 4; i++)
#pragma unroll
        for (int j = 0; j < 4; j++)
#pragma unroll
            for (int q = 0; q < 4; q++) acc[i][j][q] = 0.f;

    for (int ck = 0; ck < 4; ck++) {
        const float4* src = (const float4*)(xp + (size_t)(ck * 64 + kr) * KD + f0 + fq);
        float4 v[8];
#pragma unroll
        for (int q = 0; q < 8; q++) v[q] = src[q];
        __syncthreads();
#pragma unroll
        for (int q = 0; q < 8; q++) {
#pragma unroll
            for (int j = 0; j < 4; j++) {
                int f = fq + q * 4 + j;
                ((__half*)pAH)[f * 72 + kr] = __float2half((&v[q].x)[j]);
            }
        }
        __syncthreads();
#pragma unroll
        for (int kk = 0; kk < 4; kk++) {
            const int kh = kk * 8;
            const int kg = ck * 64 + kk * 16 + tg * 2;
            uint32_t Ah[4][4], Bh[4][2];
#pragma unroll
            for (int mt = 0; mt < 4; mt++) {
                int mr = wf * 64 + mt * 16;
                Ah[mt][0] = pAH[(mr + g) * 36 + kh + tg];
                Ah[mt][1] = pAH[(mr + g + 8) * 36 + kh + tg];
                Ah[mt][2] = pAH[(mr + g) * 36 + kh + tg + 4];
                Ah[mt][3] = pAH[(mr + g + 8) * 36 + kh + tg + 4];
            }
#pragma unroll
            for (int nt = 0; nt < 4; nt++) {
                int i = i0 + wi * 32 + nt * 8 + g;
                Bh[nt][0] = *(const uint32_t*)(Uhp + (size_t)i * 256 + kg);
                Bh[nt][1] = *(const uint32_t*)(Uhp + (size_t)i * 256 + kg + 8);
            }
#pragma unroll
            for (int mt = 0; mt < 4; mt++)
#pragma unroll
                for (int nt = 0; nt < 4; nt++)
                    hmma_hf(acc[mt][nt], Ah[mt], Bh[nt]);
        }
    }
    float* Y = g_y4 + (size_t)b * PB;
#pragma unroll
    for (int mt = 0; mt < 4; mt++)
#pragma unroll
        for (int nt = 0; nt < 4; nt++) {
            int f = f0 + wf * 64 + mt * 16 + g;
            int il = wi * 32 + nt * 8 + tg * 2;
            float b0 = sbeta[il], b1 = sbeta[il + 1];
            int i = i0 + il;
            *(float2*)(Y + (size_t)f * 256 + i) = make_float2(acc[mt][nt][0] + b0, acc[mt][nt][1] + b1);
            *(float2*)(Y + (size_t)(f + 8) * 256 + i) = make_float2(acc[mt][nt][2] + b0, acc[mt][nt][3] + b1);
        }
}

// ---- K4: out = wW @ y4 + bW + x ----
__global__ void __launch_bounds__(256) k4(const float* __restrict__ wW, const float* __restrict__ bW,
                                          const float* __restrict__ x, float* __restrict__ out) {
    const int p0 = blockIdx.x * 64, b = blockIdx.y;
    __shared__ float Ws[64][64], Ys[64][64];
    const int t = threadIdx.x;
    for (int idx = t; idx < 4096; idx += 256) Ws[idx & 63][idx >> 6] = wW[idx];
    const float* Y = g_y4 + (size_t)b * PB + p0;
    for (int idx = t; idx < 1024; idx += 256) {
        int k = idx >> 4, p4 = (idx & 15) * 4;
        *(float4*)(&Ys[k][p4]) = *(const float4*)(Y + (size_t)k * 65536 + p4);
    }
    __syncthreads();
    const int ty = t >> 4, tx = t & 15;
    float acc[4][4];
#pragma unroll
    for (int u = 0; u < 4; u++)
#pragma unroll
        for (int v = 0; v < 4; v++) acc[u][v] = 0.f;
    for (int k = 0; k < 64; k++) {
        float af[4], bf[4];
        *(float4*)af = *(const float4*)(&Ws[k][ty * 4]);
        *(float4*)bf = *(const float4*)(&Ys[k][tx * 4]);
#pragma unroll
        for (int u = 0; u < 4; u++)
#pragma unroll
            for (int v = 0; v < 4; v++) acc[u][v] = fmaf(af[u], bf[v], acc[u][v]);
    }
#pragma unroll
    for (int u = 0; u < 4; u++) {
        int o = ty * 4 + u;
        size_t base = (size_t)b * PB + (size_t)o * 65536 + p0 + tx * 4;
        float4 xr = *(const float4*)(x + base);
        float bw = __ldg(&bW[o]);
        float4 w = make_float4(acc[u][0] + bw + xr.x, acc[u][1] + bw + xr.y,
                               acc[u][2] + bw + xr.z, acc[u][3] + bw + xr.w);
        *(float4*)(out + base) = w;
    }
}

extern "C" void kernel_launch(void* const* d_in, const int* in_sizes, int n_in,
                              void* d_out, int out_size) {
    const float* x    = (const float*)d_in[0];
    const float* ref  = (const float*)d_in[1];
    const float* w_g  = (const float*)d_in[2];
    const float* b_g  = (const float*)d_in[3];
    const float* w_th = (const float*)d_in[4];
    const float* b_th = (const float*)d_in[5];
    const float* w_ph = (const float*)d_in[6];
    const float* b_ph = (const float*)d_in[7];
    const float* w_W  = (const float*)d_in[8];
    const float* b_W  = (const float*)d_in[9];
    float* out = (float*)d_out;

    cudaFuncSetAttribute(k1, cudaFuncAttributeMaxDynamicSharedMemorySize, 73728);

    kz         <<<8, 256>>>();
    k1         <<<dim3(4, 8, SPLIT), 256, 73728>>>(ref, x);
    k2a_f      <<<dim3(16, 8), 256>>>(w_th, b_th, w_ph, b_ph);
    k2b_softmax<<<dim3(32, 8), 256>>>();
    k2c_u      <<<dim3(4, 8), 256>>>(w_g, b_g);
    k3         <<<dim3(256, 8), 256, 18944>>>(x);
    k4         <<<dim3(1024, 8), 256>>>(w_W, b_W, x, out);
}